// round 2
// baseline (speedup 1.0000x reference)
#include <cuda_runtime.h>
#include <cstdint>
#include <math.h>

// Problem constants: B=2, S=2048, D=1024, H=16, hd=64
#define SEQ   2048
#define DMODEL 1024
#define NH    16
#define HD    64
#define MTOT  4096   // B*S

// ---------------- scratch (no cudaMalloc allowed) ----------------
__device__ float g_Q[MTOT * DMODEL];
__device__ float g_K[MTOT * DMODEL];
__device__ float g_V[MTOT * DMODEL];

// ---------------- helpers ----------------
__device__ __forceinline__ uint32_t f2tf(float x) {
    uint32_t u;
    asm("cvt.rna.tf32.f32 %0, %1;" : "=r"(u) : "f"(x));
    return u;
}

__device__ __forceinline__ void mma8(float* c, const uint32_t* a, uint32_t b0, uint32_t b1) {
    asm volatile(
        "mma.sync.aligned.m16n8k8.row.col.f32.tf32.tf32.f32 "
        "{%0,%1,%2,%3}, {%4,%5,%6,%7}, {%8,%9}, {%0,%1,%2,%3};"
        : "+f"(c[0]), "+f"(c[1]), "+f"(c[2]), "+f"(c[3])
        : "r"(a[0]), "r"(a[1]), "r"(a[2]), "r"(a[3]), "r"(b0), "r"(b1));
}

// ======================================================================
// Kernel 1: QKV projection GEMM (unchanged from passing round).
// ======================================================================
__global__ __launch_bounds__(256) void qkv_gemm(
    const float* __restrict__ x,
    const float* __restrict__ Wq, const float* __restrict__ Wk, const float* __restrict__ Wv,
    const float* __restrict__ bq, const float* __restrict__ bk, const float* __restrict__ bv)
{
    __shared__ float As[128][36];   // pad 36: frag bank = (4g+t)%32, conflict-free
    __shared__ float Bs[32][136];   // pad 136: frag bank = (8t+g)%32, conflict-free

    const float* W; const float* bias; float* outp;
    if (blockIdx.z == 0)      { W = Wq; bias = bq; outp = g_Q; }
    else if (blockIdx.z == 1) { W = Wk; bias = bk; outp = g_K; }
    else                      { W = Wv; bias = bv; outp = g_V; }

    const int tid  = threadIdx.x;
    const int warp = tid >> 5, lane = tid & 31;
    const int g = lane >> 2, t = lane & 3;
    const int wr = warp >> 1;          // 0..3 (m)
    const int wc = warp & 1;           // 0..1 (n)
    const int m0 = blockIdx.y * 128;
    const int n0 = blockIdx.x * 128;

    float acc[2][8][4] = {};

    for (int k0 = 0; k0 < DMODEL; k0 += 32) {
        #pragma unroll
        for (int r = 0; r < 4; r++) {
            int i = tid + 256 * r;           // 0..1023
            int row = i >> 3;
            int c4  = (i & 7) << 2;
            float4 v = *(const float4*)&x[(m0 + row) * DMODEL + k0 + c4];
            As[row][c4 + 0] = __uint_as_float(f2tf(v.x));
            As[row][c4 + 1] = __uint_as_float(f2tf(v.y));
            As[row][c4 + 2] = __uint_as_float(f2tf(v.z));
            As[row][c4 + 3] = __uint_as_float(f2tf(v.w));
        }
        #pragma unroll
        for (int r = 0; r < 4; r++) {
            int i = tid + 256 * r;
            int row = i >> 5;
            int c4  = (i & 31) << 2;
            float4 v = *(const float4*)&W[(k0 + row) * DMODEL + n0 + c4];
            Bs[row][c4 + 0] = __uint_as_float(f2tf(v.x));
            Bs[row][c4 + 1] = __uint_as_float(f2tf(v.y));
            Bs[row][c4 + 2] = __uint_as_float(f2tf(v.z));
            Bs[row][c4 + 3] = __uint_as_float(f2tf(v.w));
        }
        __syncthreads();

        #pragma unroll
        for (int ks = 0; ks < 4; ks++) {
            const int kk = ks * 8;
            uint32_t a[2][4], bb[8][2];
            #pragma unroll
            for (int mt = 0; mt < 2; mt++) {
                int rb = wr * 32 + mt * 16;
                a[mt][0] = __float_as_uint(As[rb + g    ][kk + t    ]);
                a[mt][1] = __float_as_uint(As[rb + g + 8][kk + t    ]);
                a[mt][2] = __float_as_uint(As[rb + g    ][kk + t + 4]);
                a[mt][3] = __float_as_uint(As[rb + g + 8][kk + t + 4]);
            }
            #pragma unroll
            for (int nt = 0; nt < 8; nt++) {
                int cb = wc * 64 + nt * 8;
                bb[nt][0] = __float_as_uint(Bs[kk + t    ][cb + g]);
                bb[nt][1] = __float_as_uint(Bs[kk + t + 4][cb + g]);
            }
            #pragma unroll
            for (int mt = 0; mt < 2; mt++)
                #pragma unroll
                for (int nt = 0; nt < 8; nt++)
                    mma8(acc[mt][nt], a[mt], bb[nt][0], bb[nt][1]);
        }
        __syncthreads();
    }

    #pragma unroll
    for (int mt = 0; mt < 2; mt++) {
        int row = m0 + wr * 32 + mt * 16 + g;
        #pragma unroll
        for (int nt = 0; nt < 8; nt++) {
            int col = n0 + wc * 64 + nt * 8 + 2 * t;
            float b0v = bias[col], b1v = bias[col + 1];
            float2 v0 = make_float2(acc[mt][nt][0] + b0v, acc[mt][nt][1] + b1v);
            float2 v1 = make_float2(acc[mt][nt][2] + b0v, acc[mt][nt][3] + b1v);
            *(float2*)&outp[(size_t)row       * DMODEL + col] = v0;
            *(float2*)&outp[(size_t)(row + 8) * DMODEL + col] = v1;
        }
    }
}

// ======================================================================
// Kernel 2: flash attention v2.
// grid = (SEQ/128, B*NH), 256 threads (8 warps), each warp owns 16 q-rows.
// KV tiles of 32 keys.
//  - K stored in smem with (d, d+4) PAIRED layout -> S b-frags are LDS.64
//  - V stored [key][d], stride 72 -> conflict-free LDS.32 b-frags
//  - P stored with paired-col layout -> A-frag reload is LDS.64
// ======================================================================
#define KS_STRIDE 72
#define VS_STRIDE 72
#define PS_STRIDE 40

__global__ __launch_bounds__(256) void attn_kernel(float* __restrict__ out)
{
    __shared__ float Ksp[32][KS_STRIDE];   // paired-d layout
    __shared__ float Vs [32][VS_STRIDE];   // plain [key][d]
    __shared__ float Ps [128][PS_STRIDE];  // paired-col layout, 16 rows per warp

    const int tid = threadIdx.x, warp = tid >> 5, lane = tid & 31;
    const int g = lane >> 2, t = lane & 3;
    const int bh = blockIdx.y;
    const int b  = bh >> 4;
    const int h  = bh & 15;
    const int q0 = blockIdx.x * 128;

    // fill-role indices: each thread owns (key, 8-wide d-group)
    const int fkey  = tid >> 3;          // 0..31
    const int fdgrp = (tid & 7) << 3;    // 0,8,...,56

    // --- load Q fragments for this warp's 16 rows directly from global ---
    const int qrow = b * SEQ + q0 + warp * 16;
    uint32_t qa[8][4];
    #pragma unroll
    for (int kt = 0; kt < 8; kt++) {
        qa[kt][0] = f2tf(g_Q[(size_t)(qrow + g    ) * DMODEL + h * HD + kt * 8 + t    ]);
        qa[kt][1] = f2tf(g_Q[(size_t)(qrow + g + 8) * DMODEL + h * HD + kt * 8 + t    ]);
        qa[kt][2] = f2tf(g_Q[(size_t)(qrow + g    ) * DMODEL + h * HD + kt * 8 + t + 4]);
        qa[kt][3] = f2tf(g_Q[(size_t)(qrow + g + 8) * DMODEL + h * HD + kt * 8 + t + 4]);
    }

    float m2[2]  = {-INFINITY, -INFINITY};   // running max (log2 domain)
    float ls[2]  = {0.f, 0.f};               // per-lane partial row sums
    float o[8][4] = {};

    const float* Kbase = g_K + (size_t)(b * SEQ) * DMODEL + h * HD;
    const float* Vbase = g_V + (size_t)(b * SEQ) * DMODEL + h * HD;
    const float SC = 0.125f * 1.44269504088896f;  // 1/sqrt(64) * log2(e)

    // paired-column positions for P store (col c -> (c&3)*2 + ((c>>2)&1))
    const int pkA = ((2 * t) & 3) * 2 + (((2 * t) >> 2) & 1);       // col 2t
    const int pkB = ((2 * t + 1) & 3) * 2 + (((2 * t + 1) >> 2) & 1); // col 2t+1

    for (int kv0 = 0; kv0 < SEQ; kv0 += 32) {
        // --- fill K (paired) and V (plain), convert to tf32 ---
        {
            const float* kp = Kbase + (size_t)(kv0 + fkey) * DMODEL + fdgrp;
            float4 k1 = *(const float4*)kp;
            float4 k2 = *(const float4*)(kp + 4);
            float4 s0, s1;
            s0.x = __uint_as_float(f2tf(k1.x)); s0.y = __uint_as_float(f2tf(k2.x));
            s0.z = __uint_as_float(f2tf(k1.y)); s0.w = __uint_as_float(f2tf(k2.y));
            s1.x = __uint_as_float(f2tf(k1.z)); s1.y = __uint_as_float(f2tf(k2.z));
            s1.z = __uint_as_float(f2tf(k1.w)); s1.w = __uint_as_float(f2tf(k2.w));
            *(float4*)&Ksp[fkey][fdgrp]     = s0;
            *(float4*)&Ksp[fkey][fdgrp + 4] = s1;

            const float* vp = Vbase + (size_t)(kv0 + fkey) * DMODEL + fdgrp;
            float4 v1 = *(const float4*)vp;
            float4 v2 = *(const float4*)(vp + 4);
            float4 w0, w1;
            w0.x = __uint_as_float(f2tf(v1.x)); w0.y = __uint_as_float(f2tf(v1.y));
            w0.z = __uint_as_float(f2tf(v1.z)); w0.w = __uint_as_float(f2tf(v1.w));
            w1.x = __uint_as_float(f2tf(v2.x)); w1.y = __uint_as_float(f2tf(v2.y));
            w1.z = __uint_as_float(f2tf(v2.z)); w1.w = __uint_as_float(f2tf(v2.w));
            *(float4*)&Vs[fkey][fdgrp]     = w0;
            *(float4*)&Vs[fkey][fdgrp + 4] = w1;
        }
        __syncthreads();

        // --- S = Q @ K^T : b-frags as LDS.64 from paired K ---
        float s[4][4] = {};
        #pragma unroll
        for (int nt = 0; nt < 4; nt++) {
            #pragma unroll
            for (int kt = 0; kt < 8; kt++) {
                float2 bb = *(const float2*)&Ksp[nt * 8 + g][kt * 8 + 2 * t];
                mma8(s[nt], qa[kt], __float_as_uint(bb.x), __float_as_uint(bb.y));
            }
        }

        // --- scale into log2 domain, row max (over this tile) ---
        float mx0 = -INFINITY, mx1 = -INFINITY;
        #pragma unroll
        for (int nt = 0; nt < 4; nt++) {
            s[nt][0] *= SC; s[nt][1] *= SC; s[nt][2] *= SC; s[nt][3] *= SC;
            mx0 = fmaxf(mx0, fmaxf(s[nt][0], s[nt][1]));
            mx1 = fmaxf(mx1, fmaxf(s[nt][2], s[nt][3]));
        }
        mx0 = fmaxf(mx0, __shfl_xor_sync(0xffffffffu, mx0, 1));
        mx0 = fmaxf(mx0, __shfl_xor_sync(0xffffffffu, mx0, 2));
        mx1 = fmaxf(mx1, __shfl_xor_sync(0xffffffffu, mx1, 1));
        mx1 = fmaxf(mx1, __shfl_xor_sync(0xffffffffu, mx1, 2));

        float mn0 = fmaxf(m2[0], mx0);
        float mn1 = fmaxf(m2[1], mx1);
        float c0 = exp2f(m2[0] - mn0);
        float c1 = exp2f(m2[1] - mn1);
        m2[0] = mn0; m2[1] = mn1;
        ls[0] *= c0; ls[1] *= c1;
        #pragma unroll
        for (int nt = 0; nt < 8; nt++) {
            o[nt][0] *= c0; o[nt][1] *= c0;
            o[nt][2] *= c1; o[nt][3] *= c1;
        }

        // --- P = exp2(s - m), store paired-col tf32 ---
        const int rg = warp * 16 + g;
        #pragma unroll
        for (int nt = 0; nt < 4; nt++) {
            float p0 = exp2f(s[nt][0] - mn0);
            float p1 = exp2f(s[nt][1] - mn0);
            float p2 = exp2f(s[nt][2] - mn1);
            float p3 = exp2f(s[nt][3] - mn1);
            ls[0] += p0 + p1;
            ls[1] += p2 + p3;
            Ps[rg    ][nt * 8 + pkA] = __uint_as_float(f2tf(p0));
            Ps[rg    ][nt * 8 + pkB] = __uint_as_float(f2tf(p1));
            Ps[rg + 8][nt * 8 + pkA] = __uint_as_float(f2tf(p2));
            Ps[rg + 8][nt * 8 + pkB] = __uint_as_float(f2tf(p3));
        }
        __syncwarp();

        // --- reload P as A-frags via LDS.64 ---
        uint32_t pa[4][4];
        #pragma unroll
        for (int kt = 0; kt < 4; kt++) {
            float2 u0 = *(const float2*)&Ps[rg    ][kt * 8 + 2 * t];
            float2 u1 = *(const float2*)&Ps[rg + 8][kt * 8 + 2 * t];
            pa[kt][0] = __float_as_uint(u0.x);
            pa[kt][1] = __float_as_uint(u1.x);
            pa[kt][2] = __float_as_uint(u0.y);
            pa[kt][3] = __float_as_uint(u1.y);
        }

        // --- O += P @ V ---
        #pragma unroll
        for (int nt = 0; nt < 8; nt++) {
            #pragma unroll
            for (int kt = 0; kt < 4; kt++) {
                uint32_t b0 = __float_as_uint(Vs[kt * 8 + t    ][nt * 8 + g]);
                uint32_t b1 = __float_as_uint(Vs[kt * 8 + t + 4][nt * 8 + g]);
                mma8(o[nt], pa[kt], b0, b1);
            }
        }
        __syncthreads();
    }

    // --- normalize and write out[b, s, h*64 + d] ---
    ls[0] += __shfl_xor_sync(0xffffffffu, ls[0], 1);
    ls[0] += __shfl_xor_sync(0xffffffffu, ls[0], 2);
    ls[1] += __shfl_xor_sync(0xffffffffu, ls[1], 1);
    ls[1] += __shfl_xor_sync(0xffffffffu, ls[1], 2);
    float i0 = 1.f / ls[0];
    float i1 = 1.f / ls[1];

    const int orow = b * SEQ + q0 + warp * 16;
    #pragma unroll
    for (int nt = 0; nt < 8; nt++) {
        int col = h * HD + nt * 8 + 2 * t;
        float2 v0 = make_float2(o[nt][0] * i0, o[nt][1] * i0);
        float2 v1 = make_float2(o[nt][2] * i1, o[nt][3] * i1);
        *(float2*)&out[(size_t)(orow + g    ) * DMODEL + col] = v0;
        *(float2*)&out[(size_t)(orow + g + 8) * DMODEL + col] = v1;
    }
}

// ======================================================================
// launch
// ======================================================================
extern "C" void kernel_launch(void* const* d_in, const int* in_sizes, int n_in,
                              void* d_out, int out_size)
{
    const float* x  = (const float*)d_in[0];
    const float* Wq = (const float*)d_in[1];
    const float* bq = (const float*)d_in[2];
    const float* Wk = (const float*)d_in[3];
    const float* bk = (const float*)d_in[4];
    const float* Wv = (const float*)d_in[5];
    const float* bv = (const float*)d_in[6];
    float* out = (float*)d_out;

    dim3 gg(DMODEL / 128, MTOT / 128, 3);   // (8, 32, 3)
    qkv_gemm<<<gg, 256>>>(x, Wq, Wk, Wv, bq, bk, bv);

    dim3 ga(SEQ / 128, 2 * NH);             // (16, 32)
    attn_kernel<<<ga, 256>>>(out);
}